// round 10
// baseline (speedup 1.0000x reference)
#include <cuda_runtime.h>
#include <math.h>

// Problem constants
#define B 8
#define L 256
#define D 16
#define H 128
#define DFF 128
#define EPSV 1e-6f

#define TI 16       // query rows per block
#define RI 8        // i-rows per thread
#define NBLK 128    // grid size (all co-resident: 128 <= 148 SMs @ 1 CTA/SM)

typedef unsigned long long u64;

// Scratch (device globals)
__device__ float  g_v   [B * L * D];
__device__ float4 g_kbaT[B * (H/2) * L];  // [b][hp][j] = (kb[2hp],kb[2hp+1],ka[2hp],ka[2hp+1])
__device__ unsigned int g_bar;            // grid barrier ticket counter (monotonic)

// ---------------- packed f32x2 helpers ----------------
__device__ __forceinline__ u64 add2(u64 a, u64 b) {
    u64 d; asm("add.rn.f32x2 %0,%1,%2;" : "=l"(d) : "l"(a), "l"(b)); return d;
}
__device__ __forceinline__ u64 fma2(u64 a, u64 b, u64 c) {
    u64 d; asm("fma.rn.f32x2 %0,%1,%2,%3;" : "=l"(d) : "l"(a), "l"(b), "l"(c)); return d;
}
__device__ __forceinline__ u64 relu2(u64 v) {
    float lo, hi;
    asm("mov.b64 {%0,%1}, %2;" : "=f"(lo), "=f"(hi) : "l"(v));
    lo = fmaxf(lo, 0.f); hi = fmaxf(hi, 0.f);
    u64 d; asm("mov.b64 %0,{%1,%2};" : "=l"(d) : "f"(lo), "f"(hi)); return d;
}
__device__ __forceinline__ float redu2(u64 v) {
    float lo, hi;
    asm("mov.b64 {%0,%1}, %2;" : "=f"(lo), "=f"(hi) : "l"(v));
    return lo + hi;
}
__device__ __forceinline__ void cpa16(void* dst_smem, const void* src_gmem) {
    unsigned d = (unsigned)__cvta_generic_to_shared(dst_smem);
    asm volatile("cp.async.cg.shared.global [%0], [%1], 16;" :: "r"(d), "l"(src_gmem) : "memory");
}

// ---------------------------------------------------------------------------
// Single fused kernel. 128 blocks x 1024 threads (1 CTA/SM).
// ---------------------------------------------------------------------------
struct __align__(16) Smem {
    float qa[TI * 132];          // 2112 (written by stage A)
    float qb[TI * 132];          // 2112
    float logitsP[2][TI * L];    // 8192 ; stage-A staging, then logit partials
    float maskS[TI * L];         // 4096 ; aliased after phase 2: ctxp/fp/csum
    float vT[D * 260];           // 4160
    float w2[H];
    float wo[D * D];
    float f1[D * DFF];
    float f2T[D * 132];
    float xr[TI * D];
    float out1[TI * D];
    float f1b[DFF];
    float bo[D], f2b[D];
    float g1[D], be1[D], g2[D], be2[D];
};

__global__ __launch_bounds__(1024, 1) void k_main(
    const float* __restrict__ x,
    const float* __restrict__ mask,
    const float* __restrict__ wq, const float* __restrict__ bq,
    const float* __restrict__ wk, const float* __restrict__ bk,
    const float* __restrict__ wv, const float* __restrict__ bv,
    const float* __restrict__ wo_g, const float* __restrict__ bo_g,
    const float* __restrict__ nn_w1, const float* __restrict__ nn_b1,
    const float* __restrict__ w2_g, const float* __restrict__ b2_g,
    const float* __restrict__ f1_g, const float* __restrict__ f1b_g,
    const float* __restrict__ f2_g, const float* __restrict__ f2b_g,
    const float* __restrict__ g1_g, const float* __restrict__ be1_g,
    const float* __restrict__ g2_g, const float* __restrict__ be2_g,
    float* __restrict__ out)
{
    extern __shared__ char smem_raw[];
    Smem* s = reinterpret_cast<Smem*>(smem_raw);

    const int tid   = threadIdx.x;
    const int b     = blockIdx.x >> 4;
    const int iBase = (blockIdx.x & 15) << 4;

    // ---- mask cp.async immediately (consumed only at phase 2) ----
    {
        const float4* gm = reinterpret_cast<const float4*>(mask + (size_t)(b * L + iBase) * L);
        cpa16(reinterpret_cast<float4*>(s->maskS) + tid, gm + tid);   // 1024 f4
        asm volatile("cp.async.commit_group;" ::: "memory");
    }

    // =============== Stage A: per-block precompute (own 16 rows) ===========
    float* w1s = s->logitsP[0];              // 4096 = 32 x 128  (nn_w1)
    float* xs  = s->logitsP[1];              // 256  = 16 x 16
    float* stQ = s->logitsP[1] + 256;        // 256
    float* stK = s->logitsP[1] + 512;        // 256
    float* b1s = s->logitsP[1] + 768;        // 128

    reinterpret_cast<float4*>(w1s)[tid] = reinterpret_cast<const float4*>(nn_w1)[tid]; // 4096 floats
    if (tid < 256) {
        xs[tid]    = x[(b * L + iBase) * D + tid];
        s->xr[tid] = xs[tid];
    }
    if (tid < 128) b1s[tid] = nn_b1[tid];
    __syncthreads();

    const int rowA = tid >> 6;      // 0..15
    const int l64  = tid & 63;
    if (l64 < 48) {
        const int c = l64 & 15;
        const float* W    = (l64 < 16) ? wq : (l64 < 32 ? wk : wv);
        const float* bias = (l64 < 16) ? bq : (l64 < 32 ? bk : bv);
        float a = bias[c];
        #pragma unroll
        for (int d = 0; d < D; ++d) a = fmaf(xs[rowA * D + d], W[d * D + c], a);
        if      (l64 < 16) stQ[rowA * D + c] = a;
        else if (l64 < 32) stK[rowA * D + c] = a;
        else               g_v[(b * L + iBase + rowA) * D + c] = a;
    }
    __syncthreads();

    {
        const int hp = l64;             // 0..63
        const int h0 = hp * 2;
        float qa0 = 0.f, qa1 = 0.f, qb0 = 0.f, qb1 = 0.f;
        float kb0 = b1s[h0], kb1 = b1s[h0 + 1];
        float ka0 = b1s[h0], ka1 = b1s[h0 + 1];
        #pragma unroll
        for (int d = 0; d < D; ++d) {
            const float qd = stQ[rowA * D + d];
            const float kd = stK[rowA * D + d];
            const float w1q0 = w1s[d * H + h0],        w1q1 = w1s[d * H + h0 + 1];
            const float w1k0 = w1s[(d + D) * H + h0],  w1k1 = w1s[(d + D) * H + h0 + 1];
            qa0 = fmaf(qd, w1q0, qa0);  qa1 = fmaf(qd, w1q1, qa1);
            qb0 = fmaf(qd, w1k0, qb0);  qb1 = fmaf(qd, w1k1, qb1);
            kb0 = fmaf(kd, w1k0, kb0);  kb1 = fmaf(kd, w1k1, kb1);
            ka0 = fmaf(kd, w1q0, ka0);  ka1 = fmaf(kd, w1q1, ka1);
        }
        s->qa[rowA * 132 + h0] = qa0;  s->qa[rowA * 132 + h0 + 1] = qa1;
        s->qb[rowA * 132 + h0] = qb0;  s->qb[rowA * 132 + h0 + 1] = qb1;
        g_kbaT[(size_t)(b * (H/2) + hp) * L + (iBase + rowA)] = make_float4(kb0, kb1, ka0, ka1);
    }

    // ---- independent smem fills (no cross-block deps) before the barrier --
    {
        #pragma unroll
        for (int r = 0; r < 2; ++r) {
            const int e = tid + 1024 * r;              // < 2048
            const int h = e >> 4, d = e & 15;
            s->f2T[d * 132 + h] = f2_g[e];
        }
        if (tid < 512)
            reinterpret_cast<float4*>(s->f1)[tid] = reinterpret_cast<const float4*>(f1_g)[tid];
        if (tid < H)   { s->w2[tid] = w2_g[tid]; s->f1b[tid] = f1b_g[tid]; }
        if (tid < 256) s->wo[tid] = wo_g[tid];
        if (tid < D) {
            s->bo[tid]  = bo_g[tid];  s->f2b[tid] = f2b_g[tid];
            s->g1[tid]  = g1_g[tid];  s->be1[tid] = be1_g[tid];
            s->g2[tid]  = g2_g[tid];  s->be2[tid] = be2_g[tid];
        }
    }
    const float b2x2 = 2.f * b2_g[0];

    // =============== Grid spin barrier (all 128 CTAs co-resident) ==========
    __syncthreads();
    __threadfence();
    if (tid == 0) {
        const unsigned int ticket = atomicAdd(&g_bar, 1u);
        const unsigned int target = (ticket / NBLK + 1u) * NBLK;
        volatile unsigned int* p = &g_bar;
        while (*p < target) {}
        __threadfence();
    }
    __syncthreads();

    // vT: transpose v[j][d] -> vT[d][260] (needs other blocks' g_v)
    {
        const float4 val = reinterpret_cast<const float4*>(g_v + b * L * D)[tid];  // 1024 f4
        const int j = tid >> 2, dq = tid & 3;
        s->vT[(dq * 4 + 0) * 260 + j] = val.x;
        s->vT[(dq * 4 + 1) * 260 + j] = val.y;
        s->vT[(dq * 4 + 2) * 260 + j] = val.z;
        s->vT[(dq * 4 + 3) * 260 + j] = val.w;
    }

    // ---------------- Phase 1: pairwise-MLP logits (barrier-free) ----------
    const int j  = tid & 255;          // fixed key column
    const int g  = (tid >> 8) & 1;     // i-half: rows g*8 .. g*8+7
    const int hh = tid >> 9;           // h-half: hp in [hh*32, hh*32+32)

    const ulonglong2* gkba = reinterpret_cast<const ulonglong2*>(g_kbaT)
                             + (size_t)(b * (H/2) + hh * 32) * L + j;
    const ulonglong2* qaB = reinterpret_cast<const ulonglong2*>(s->qa) + (g * RI) * 33 + hh * 16;
    const ulonglong2* qbB = reinterpret_cast<const ulonglong2*>(s->qb) + (g * RI) * 33 + hh * 16;
    const ulonglong2* w2p = reinterpret_cast<const ulonglong2*>(s->w2) + hh * 16;

    u64 acc[RI];
    #pragma unroll
    for (int r = 0; r < RI; ++r) acc[r] = 0ull;

    // warp-staggered chunk ring: 8 distinct starts per SMSP decorrelate the
    // LDG-consume points so co-resident warps cover each other's L2 latency.
    int c = ((tid >> 7) * 2) & 15;     // (wid>>2)*2 & 15

    ulonglong2 C0 = gkba[(2 * c) * L];
    ulonglong2 C1 = gkba[(2 * c + 1) * L];

    #pragma unroll 4
    for (int it = 0; it < 16; ++it) {     // 16 chunks of 4 h (2 hp), ring order
        const int cn = (c + 1) & 15;
        ulonglong2 N0, N1;
        if (it < 15) {
            N0 = gkba[(2 * cn) * L];
            N1 = gkba[(2 * cn + 1) * L];
        }
        const ulonglong2 W = w2p[c];
        #pragma unroll
        for (int r = 0; r < RI; ++r) {
            const ulonglong2 a  = qaB[r * 33 + c];
            const ulonglong2 bb = qbB[r * 33 + c];
            acc[r] = fma2(add2(relu2(add2(a.x, C0.x)), relu2(add2(bb.x, C0.y))), W.x, acc[r]);
            acc[r] = fma2(add2(relu2(add2(a.y, C1.x)), relu2(add2(bb.y, C1.y))), W.y, acc[r]);
        }
        C0 = N0; C1 = N1;
        c = cn;
    }

    __syncthreads();   // staging in logitsP fully consumed block-wide
    #pragma unroll
    for (int r = 0; r < RI; ++r)
        s->logitsP[hh][(g * RI + r) * L + j] = redu2(acc[r]);

    asm volatile("cp.async.wait_group 0;" ::: "memory");
    __syncthreads();

    // ---------------- Phase 2: softmax (warps 0-15, 1 row each) ------------
    if (tid < 512) {
        const int r = tid >> 5, lane = tid & 31;
        const float* lp0 = s->logitsP[0] + r * L;
        const float* lp1 = s->logitsP[1] + r * L;
        const float* mr  = s->maskS + r * L;
        float vals[8];
        float mx = -INFINITY;
        #pragma unroll
        for (int t = 0; t < 8; ++t) {
            const int jj = lane + 32 * t;
            const float lg = lp0[jj] + lp1[jj] + b2x2 + mr[jj] * (-1e9f);
            vals[t] = lg;
            mx = fmaxf(mx, lg);
        }
        #pragma unroll
        for (int m = 16; m > 0; m >>= 1)
            mx = fmaxf(mx, __shfl_xor_sync(0xffffffffu, mx, m));
        float sum = 0.f;
        #pragma unroll
        for (int t = 0; t < 8; ++t) { vals[t] = __expf(vals[t] - mx); sum += vals[t]; }
        #pragma unroll
        for (int m = 16; m > 0; m >>= 1)
            sum += __shfl_xor_sync(0xffffffffu, sum, m);
        const float inv = 1.f / sum;
        #pragma unroll
        for (int t = 0; t < 8; ++t)
            s->logitsP[0][r * L + lane + 32 * t] = vals[t] * inv;
    }
    __syncthreads();

    // aliased scratch
    float* ctxp   = s->maskS;            // 1024
    float* fp     = s->maskS + 1024;     // 1024
    float* csum   = s->maskS + 2048;     // 256
    float* hidden = s->logitsP[1];       // 2048 (partials dead after phase 2)

    // ---------------- Phase 3: ctx = attn @ v (4 j-quarters) ---------------
    {
        const int q = tid >> 8, p = tid & 255;
        const int il = p >> 4, dl = p & 15;
        const float4* arow = reinterpret_cast<const float4*>(s->logitsP[0] + il * L + q * 64);
        const float4* vrow = reinterpret_cast<const float4*>(s->vT + dl * 260 + q * 64);
        float c2 = 0.f;
        #pragma unroll
        for (int t = 0; t < 16; ++t) {
            const float4 a4 = arow[t];
            const float4 v4 = vrow[t];
            c2 = fmaf(a4.x, v4.x, c2);
            c2 = fmaf(a4.y, v4.y, c2);
            c2 = fmaf(a4.z, v4.z, c2);
            c2 = fmaf(a4.w, v4.w, c2);
        }
        ctxp[q * 256 + p] = c2;
    }
    __syncthreads();

    // attn_out + residual + LN1 (first 256 threads)
    if (tid < 256) {
        const int il = tid >> 4, dl = tid & 15;
        csum[tid] = ctxp[tid] + ctxp[256 + tid] + ctxp[512 + tid] + ctxp[768 + tid];
        __syncwarp();
        float ao = s->bo[dl];
        #pragma unroll
        for (int e = 0; e < D; ++e)
            ao = fmaf(csum[il * D + e], s->wo[e * D + dl], ao);
        const float hval = s->xr[tid] + ao;   // RES=1
        float m = hval, sq = hval * hval;
        #pragma unroll
        for (int msk = 8; msk > 0; msk >>= 1) {
            m  += __shfl_xor_sync(0xffffffffu, m,  msk);
            sq += __shfl_xor_sync(0xffffffffu, sq, msk);
        }
        m *= (1.f / 16.f);
        const float var = sq * (1.f / 16.f) - m * m;
        s->out1[tid] = (hval - m) * rsqrtf(var + EPSV) * s->g1[dl] + s->be1[dl];
    }
    __syncthreads();

    // ---------------- Phase 4: FFN hidden (1024 threads, 2 i's each) -------
    {
        const int h = tid & 127;
        const int grp = tid >> 7;     // 0..7
        #pragma unroll
        for (int cc = 0; cc < 2; ++cc) {
            const int il = grp * 2 + cc;
            float a2 = s->f1b[h];
            #pragma unroll
            for (int d = 0; d < D; ++d)
                a2 = fmaf(s->out1[il * D + d], s->f1[d * DFF + h], a2);
            hidden[il * DFF + h] = fmaxf(a2, 0.f);
        }
    }
    __syncthreads();

    // f2 contraction (f2T, float4), 4 h-quarters
    {
        const int q = tid >> 8, p = tid & 255;
        const int il = p >> 4, dl = p & 15;
        const float4* hrow = reinterpret_cast<const float4*>(hidden + il * DFF + q * 32);
        const float4* frow = reinterpret_cast<const float4*>(s->f2T + dl * 132 + q * 32);
        float f = 0.f;
        #pragma unroll
        for (int t = 0; t < 8; ++t) {
            const float4 h4 = hrow[t];
            const float4 f4 = frow[t];
            f = fmaf(h4.x, f4.x, f);
            f = fmaf(h4.y, f4.y, f);
            f = fmaf(h4.z, f4.z, f);
            f = fmaf(h4.w, f4.w, f);
        }
        fp[q * 256 + p] = f;
    }
    __syncthreads();

    if (tid < 256) {
        const int il = tid >> 4, dl = tid & 15;
        const float f = s->f2b[dl] + fp[tid] + fp[256 + tid] + fp[512 + tid] + fp[768 + tid];
        const float hval = s->out1[tid] + f;   // RES=1
        float m = hval, sq = hval * hval;
        #pragma unroll
        for (int msk = 8; msk > 0; msk >>= 1) {
            m  += __shfl_xor_sync(0xffffffffu, m,  msk);
            sq += __shfl_xor_sync(0xffffffffu, sq, msk);
        }
        m *= (1.f / 16.f);
        const float var = sq * (1.f / 16.f) - m * m;
        const float o = (hval - m) * rsqrtf(var + EPSV) * s->g2[dl] + s->be2[dl];
        out[(size_t)(b * L + iBase + il) * D + dl] = o;
    }
}

// ---------------------------------------------------------------------------
extern "C" void kernel_launch(void* const* d_in, const int* in_sizes, int n_in,
                              void* d_out, int out_size)
{
    const float* x     = (const float*)d_in[0];
    const float* mask  = (const float*)d_in[1];
    const float* wq    = (const float*)d_in[2];
    const float* bq    = (const float*)d_in[3];
    const float* wk    = (const float*)d_in[4];
    const float* bk    = (const float*)d_in[5];
    const float* wv    = (const float*)d_in[6];
    const float* bv    = (const float*)d_in[7];
    const float* wo    = (const float*)d_in[8];
    const float* bo    = (const float*)d_in[9];
    const float* nn_w1 = (const float*)d_in[10];
    const float* nn_b1 = (const float*)d_in[11];
    const float* nn_w2 = (const float*)d_in[12];
    const float* nn_b2 = (const float*)d_in[13];
    const float* f1    = (const float*)d_in[14];
    const float* f1b   = (const float*)d_in[15];
    const float* f2    = (const float*)d_in[16];
    const float* f2b   = (const float*)d_in[17];
    const float* g1    = (const float*)d_in[18];
    const float* be1   = (const float*)d_in[19];
    const float* g2    = (const float*)d_in[20];
    const float* be2   = (const float*)d_in[21];
    float* out = (float*)d_out;

    cudaFuncSetAttribute(k_main, cudaFuncAttributeMaxDynamicSharedMemorySize,
                         (int)sizeof(Smem));

    k_main<<<NBLK, 1024, sizeof(Smem)>>>(
        x, mask, wq, bq, wk, bk, wv, bv, wo, bo, nn_w1, nn_b1,
        nn_w2, nn_b2, f1, f1b, f2, f2b, g1, be1, g2, be2, out);
}

// round 12
// speedup vs baseline: 1.1643x; 1.1643x over previous
#include <cuda_runtime.h>
#include <cuda_fp16.h>
#include <math.h>

// Problem constants
#define B 8
#define L 256
#define D 16
#define H 128
#define DFF 128
#define EPSV 1e-6f

#define TI 16       // query rows per block
#define RI 8        // i-rows per thread
#define NBLK 128    // grid size (all co-resident: 128 <= 148 SMs @ 1 CTA/SM)

typedef unsigned long long u64;

// Scratch (device globals)
__device__ float  g_v   [B * L * D];
// [b][hq][j] : hq = 4-h group; uint4 = {kb(h0,h1), kb(h2,h3), ka(h0,h1), ka(h2,h3)} as f16x2 words
__device__ uint4  g_kbaT[B * (H/4) * L];
__device__ unsigned int g_bar;            // grid barrier ticket counter (monotonic)

// ---------------- helpers ----------------
__device__ __forceinline__ __half2 h2(unsigned u) {
    __half2 r; *reinterpret_cast<unsigned*>(&r) = u; return r;
}
__device__ __forceinline__ unsigned hbits(__half2 v) {
    return *reinterpret_cast<unsigned*>(&v);
}
__device__ __forceinline__ void cpa16(void* dst_smem, const void* src_gmem) {
    unsigned d = (unsigned)__cvta_generic_to_shared(dst_smem);
    asm volatile("cp.async.cg.shared.global [%0], [%1], 16;" :: "r"(d), "l"(src_gmem) : "memory");
}

// ---------------------------------------------------------------------------
// Single fused kernel. 128 blocks x 1024 threads (1 CTA/SM).
// ---------------------------------------------------------------------------
struct __align__(16) Smem {
    unsigned qa16[TI * 66];      // f16x2 words, 64/row + pad
    unsigned qb16[TI * 66];
    unsigned w2h[H / 2];         // f16x2
    float logitsP[2][TI * L];    // stage-A staging, then logit partials
    float maskS[TI * L];         // aliased after phase 2: ctxp/fp/csum
    float vT[D * 260];
    float wo[D * D];
    float f1[D * DFF];
    float f2T[D * 132];
    float xr[TI * D];
    float out1[TI * D];
    float f1b[DFF];
    float bo[D], f2b[D];
    float g1[D], be1[D], g2[D], be2[D];
};

__global__ __launch_bounds__(1024, 1) void k_main(
    const float* __restrict__ x,
    const float* __restrict__ mask,
    const float* __restrict__ wq, const float* __restrict__ bq,
    const float* __restrict__ wk, const float* __restrict__ bk,
    const float* __restrict__ wv, const float* __restrict__ bv,
    const float* __restrict__ wo_g, const float* __restrict__ bo_g,
    const float* __restrict__ nn_w1, const float* __restrict__ nn_b1,
    const float* __restrict__ w2_g, const float* __restrict__ b2_g,
    const float* __restrict__ f1_g, const float* __restrict__ f1b_g,
    const float* __restrict__ f2_g, const float* __restrict__ f2b_g,
    const float* __restrict__ g1_g, const float* __restrict__ be1_g,
    const float* __restrict__ g2_g, const float* __restrict__ be2_g,
    float* __restrict__ out)
{
    extern __shared__ char smem_raw[];
    Smem* s = reinterpret_cast<Smem*>(smem_raw);

    const int tid   = threadIdx.x;
    const int b     = blockIdx.x >> 4;
    const int iBase = (blockIdx.x & 15) << 4;

    // ---- mask cp.async immediately (consumed only at phase 2) ----
    {
        const float4* gm = reinterpret_cast<const float4*>(mask + (size_t)(b * L + iBase) * L);
        cpa16(reinterpret_cast<float4*>(s->maskS) + tid, gm + tid);   // 1024 f4
        asm volatile("cp.async.commit_group;" ::: "memory");
    }

    // =============== Stage A: per-block precompute (own 16 rows) ===========
    float* w1s = s->logitsP[0];              // 4096 = 32 x 128  (nn_w1)
    float* xs  = s->logitsP[1];              // 256
    float* stQ = s->logitsP[1] + 256;        // 256
    float* stK = s->logitsP[1] + 512;        // 256
    float* b1s = s->logitsP[1] + 768;        // 128

    reinterpret_cast<float4*>(w1s)[tid] = reinterpret_cast<const float4*>(nn_w1)[tid]; // 4096 floats
    if (tid < 256) {
        xs[tid]    = x[(b * L + iBase) * D + tid];
        s->xr[tid] = xs[tid];
    }
    if (tid < 128) b1s[tid] = nn_b1[tid];
    __syncthreads();

    const int rowA = tid >> 6;      // 0..15
    const int l64  = tid & 63;
    if (l64 < 48) {
        const int c = l64 & 15;
        const float* W    = (l64 < 16) ? wq : (l64 < 32 ? wk : wv);
        const float* bias = (l64 < 16) ? bq : (l64 < 32 ? bk : bv);
        float a = bias[c];
        #pragma unroll
        for (int d = 0; d < D; ++d) a = fmaf(xs[rowA * D + d], W[d * D + c], a);
        if      (l64 < 16) stQ[rowA * D + c] = a;
        else if (l64 < 32) stK[rowA * D + c] = a;
        else               g_v[(b * L + iBase + rowA) * D + c] = a;
    }
    __syncthreads();

    {
        const int hp = l64;             // 0..63  (pair of h)
        const int h0 = hp * 2;
        float qa0 = 0.f, qa1 = 0.f, qb0 = 0.f, qb1 = 0.f;
        float kb0 = b1s[h0], kb1 = b1s[h0 + 1];
        float ka0 = b1s[h0], ka1 = b1s[h0 + 1];
        #pragma unroll
        for (int d = 0; d < D; ++d) {
            const float qd = stQ[rowA * D + d];
            const float kd = stK[rowA * D + d];
            const float w1q0 = w1s[d * H + h0],        w1q1 = w1s[d * H + h0 + 1];
            const float w1k0 = w1s[(d + D) * H + h0],  w1k1 = w1s[(d + D) * H + h0 + 1];
            qa0 = fmaf(qd, w1q0, qa0);  qa1 = fmaf(qd, w1q1, qa1);
            qb0 = fmaf(qd, w1k0, qb0);  qb1 = fmaf(qd, w1k1, qb1);
            kb0 = fmaf(kd, w1k0, kb0);  kb1 = fmaf(kd, w1k1, kb1);
            ka0 = fmaf(kd, w1q0, ka0);  ka1 = fmaf(kd, w1q1, ka1);
        }
        // fp16 packing
        s->qa16[rowA * 66 + hp] = hbits(__floats2half2_rn(qa0, qa1));
        s->qb16[rowA * 66 + hp] = hbits(__floats2half2_rn(qb0, qb1));
        const int hq = hp >> 1, sub = hp & 1;
        unsigned* dst = reinterpret_cast<unsigned*>(g_kbaT)
                        + ((((size_t)(b * (H/4) + hq)) * L + (iBase + rowA)) << 2);
        dst[sub]     = hbits(__floats2half2_rn(kb0, kb1));
        dst[2 + sub] = hbits(__floats2half2_rn(ka0, ka1));
    }

    // ---- independent smem fills (no cross-block deps) before the barrier --
    {
        #pragma unroll
        for (int r = 0; r < 2; ++r) {
            const int e = tid + 1024 * r;              // < 2048
            const int h = e >> 4, d = e & 15;
            s->f2T[d * 132 + h] = f2_g[e];
        }
        if (tid < 512)
            reinterpret_cast<float4*>(s->f1)[tid] = reinterpret_cast<const float4*>(f1_g)[tid];
        if (tid < 64)  s->w2h[tid] = hbits(__floats2half2_rn(w2_g[2 * tid], w2_g[2 * tid + 1]));
        if (tid < 128) s->f1b[tid] = f1b_g[tid];
        if (tid < 256) s->wo[tid]  = wo_g[tid];
        if (tid < D) {
            s->bo[tid]  = bo_g[tid];  s->f2b[tid] = f2b_g[tid];
            s->g1[tid]  = g1_g[tid];  s->be1[tid] = be1_g[tid];
            s->g2[tid]  = g2_g[tid];  s->be2[tid] = be2_g[tid];
        }
    }
    const float b2x2 = 2.f * b2_g[0];

    // =============== Grid spin barrier (all 128 CTAs co-resident) ==========
    __syncthreads();
    __threadfence();
    if (tid == 0) {
        const unsigned int ticket = atomicAdd(&g_bar, 1u);
        const unsigned int target = (ticket / NBLK + 1u) * NBLK;
        volatile unsigned int* p = &g_bar;
        while (*p < target) {}
        __threadfence();
    }
    __syncthreads();

    // vT: transpose v[j][d] -> vT[d][260] (needs other blocks' g_v)
    {
        const float4 val = reinterpret_cast<const float4*>(g_v + b * L * D)[tid];  // 1024 f4
        const int j = tid >> 2, dq = tid & 3;
        s->vT[(dq * 4 + 0) * 260 + j] = val.x;
        s->vT[(dq * 4 + 1) * 260 + j] = val.y;
        s->vT[(dq * 4 + 2) * 260 + j] = val.z;
        s->vT[(dq * 4 + 3) * 260 + j] = val.w;
    }

    // ---------------- Phase 1: pairwise-MLP logits (fp16x2, barrier-free) --
    const int j  = tid & 255;          // fixed key column
    const int g  = (tid >> 8) & 1;     // i-half: rows g*8 .. g*8+7
    const int hh = tid >> 9;           // h-half: hq in [hh*16, hh*16+16)

    const uint4* gkba = g_kbaT + (size_t)(b * (H/4) + hh * 16) * L + j;  // stride L per hq
    const uint2* qaB = reinterpret_cast<const uint2*>(s->qa16) + (g * RI) * 33 + hh * 16;
    const uint2* qbB = reinterpret_cast<const uint2*>(s->qb16) + (g * RI) * 33 + hh * 16;
    const uint2* w2p = reinterpret_cast<const uint2*>(s->w2h) + hh * 16;

    const __half2 z2 = __float2half2_rn(0.f);
    __half2 acc0[RI], acc1[RI];
    #pragma unroll
    for (int r = 0; r < RI; ++r) { acc0[r] = z2; acc1[r] = z2; }

    uint4 C = gkba[0];

    #pragma unroll 4
    for (int c = 0; c < 16; ++c) {     // 16 chunks of 4 h
        uint4 N;
        if (c < 15) N = gkba[(c + 1) * L];
        const __half2 kb01 = h2(C.x), kb23 = h2(C.y);
        const __half2 ka01 = h2(C.z), ka23 = h2(C.w);
        const uint2 Wp = w2p[c];
        const __half2 w01 = h2(Wp.x), w23 = h2(Wp.y);
        #pragma unroll
        for (int r = 0; r < RI; ++r) {
            const uint2 A  = qaB[r * 33 + c];
            const uint2 Bv = qbB[r * 33 + c];
            __half2 t0 = __hfma2(__hmax2(__hadd2(h2(A.x),  kb01), z2), w01, acc0[r]);
            acc0[r]    = __hfma2(__hmax2(__hadd2(h2(Bv.x), ka01), z2), w01, t0);
            __half2 t1 = __hfma2(__hmax2(__hadd2(h2(A.y),  kb23), z2), w23, acc1[r]);
            acc1[r]    = __hfma2(__hmax2(__hadd2(h2(Bv.y), ka23), z2), w23, t1);
        }
        C = N;
    }

    __syncthreads();   // stage-A staging in logitsP fully consumed block-wide
    #pragma unroll
    for (int r = 0; r < RI; ++r) {
        const float2 u  = __half22float2(acc0[r]);
        const float2 v2 = __half22float2(acc1[r]);
        s->logitsP[hh][(g * RI + r) * L + j] = (u.x + u.y) + (v2.x + v2.y);
    }

    asm volatile("cp.async.wait_group 0;" ::: "memory");
    __syncthreads();

    // ---------------- Phase 2: softmax (warps 0-15, 1 row each) ------------
    if (tid < 512) {
        const int r = tid >> 5, lane = tid & 31;
        const float* lp0 = s->logitsP[0] + r * L;
        const float* lp1 = s->logitsP[1] + r * L;
        const float* mr  = s->maskS + r * L;
        float vals[8];
        float mx = -INFINITY;
        #pragma unroll
        for (int t = 0; t < 8; ++t) {
            const int jj = lane + 32 * t;
            const float lg = lp0[jj] + lp1[jj] + b2x2 + mr[jj] * (-1e9f);
            vals[t] = lg;
            mx = fmaxf(mx, lg);
        }
        #pragma unroll
        for (int m = 16; m > 0; m >>= 1)
            mx = fmaxf(mx, __shfl_xor_sync(0xffffffffu, mx, m));
        float sum = 0.f;
        #pragma unroll
        for (int t = 0; t < 8; ++t) { vals[t] = __expf(vals[t] - mx); sum += vals[t]; }
        #pragma unroll
        for (int m = 16; m > 0; m >>= 1)
            sum += __shfl_xor_sync(0xffffffffu, sum, m);
        const float inv = 1.f / sum;
        #pragma unroll
        for (int t = 0; t < 8; ++t)
            s->logitsP[0][r * L + lane + 32 * t] = vals[t] * inv;
    }
    __syncthreads();

    // aliased scratch
    float* ctxp   = s->maskS;            // 1024
    float* fp     = s->maskS + 1024;     // 1024
    float* csum   = s->maskS + 2048;     // 256
    float* hidden = s->logitsP[1];       // 2048 (partials dead after phase 2)

    // ---------------- Phase 3: ctx = attn @ v (4 j-quarters) ---------------
    {
        const int q = tid >> 8, p = tid & 255;
        const int il = p >> 4, dl = p & 15;
        const float4* arow = reinterpret_cast<const float4*>(s->logitsP[0] + il * L + q * 64);
        const float4* vrow = reinterpret_cast<const float4*>(s->vT + dl * 260 + q * 64);
        float c2 = 0.f;
        #pragma unroll
        for (int t = 0; t < 16; ++t) {
            const float4 a4 = arow[t];
            const float4 v4 = vrow[t];
            c2 = fmaf(a4.x, v4.x, c2);
            c2 = fmaf(a4.y, v4.y, c2);
            c2 = fmaf(a4.z, v4.z, c2);
            c2 = fmaf(a4.w, v4.w, c2);
        }
        ctxp[q * 256 + p] = c2;
    }
    __syncthreads();

    // attn_out + residual + LN1 (first 256 threads)
    if (tid < 256) {
        const int il = tid >> 4, dl = tid & 15;
        csum[tid] = ctxp[tid] + ctxp[256 + tid] + ctxp[512 + tid] + ctxp[768 + tid];
        __syncwarp();
        float ao = s->bo[dl];
        #pragma unroll
        for (int e = 0; e < D; ++e)
            ao = fmaf(csum[il * D + e], s->wo[e * D + dl], ao);
        const float hval = s->xr[tid] + ao;   // RES=1
        float m = hval, sq = hval * hval;
        #pragma unroll
        for (int msk = 8; msk > 0; msk >>= 1) {
            m  += __shfl_xor_sync(0xffffffffu, m,  msk);
            sq += __shfl_xor_sync(0xffffffffu, sq, msk);
        }
        m *= (1.f / 16.f);
        const float var = sq * (1.f / 16.f) - m * m;
        s->out1[tid] = (hval - m) * rsqrtf(var + EPSV) * s->g1[dl] + s->be1[dl];
    }
    __syncthreads();

    // ---------------- Phase 4: FFN hidden (1024 threads, 2 i's each) -------
    {
        const int h = tid & 127;
        const int grp = tid >> 7;     // 0..7
        #pragma unroll
        for (int cc = 0; cc < 2; ++cc) {
            const int il = grp * 2 + cc;
            float a2 = s->f1b[h];
            #pragma unroll
            for (int d = 0; d < D; ++d)
                a2 = fmaf(s->out1[il * D + d], s->f1[d * DFF + h], a2);
            hidden[il * DFF + h] = fmaxf(a2, 0.f);
        }
    }
    __syncthreads();

    // f2 contraction (f2T, float4), 4 h-quarters
    {
        const int q = tid >> 8, p = tid & 255;
        const int il = p >> 4, dl = p & 15;
        const float4* hrow = reinterpret_cast<const float4*>(hidden + il * DFF + q * 32);
        const float4* frow = reinterpret_cast<const float4*>(s->f2T + dl * 132 + q * 32);
        float f = 0.f;
        #pragma unroll
        for (int t = 0; t < 8; ++t) {
            const float4 h4 = hrow[t];
            const float4 f4 = frow[t];
            f = fmaf(h4.x, f4.x, f);
            f = fmaf(h4.y, f4.y, f);
            f = fmaf(h4.z, f4.z, f);
            f = fmaf(h4.w, f4.w, f);
        }
        fp[q * 256 + p] = f;
    }
    __syncthreads();

    if (tid < 256) {
        const int il = tid >> 4, dl = tid & 15;
        const float f = s->f2b[dl] + fp[tid] + fp[256 + tid] + fp[512 + tid] + fp[768 + tid];
        const float hval = s->out1[tid] + f;   // RES=1
        float m = hval, sq = hval * hval;
        #pragma unroll
        for (int msk = 8; msk > 0; msk >>= 1) {
            m  += __shfl_xor_sync(0xffffffffu, m,  msk);
            sq += __shfl_xor_sync(0xffffffffu, sq, msk);
        }
        m *= (1.f / 16.f);
        const float var = sq * (1.f / 16.f) - m * m;
        const float o = (hval - m) * rsqrtf(var + EPSV) * s->g2[dl] + s->be2[dl];
        out[(size_t)(b * L + iBase + il) * D + dl] = o;
    }
}

// ---------------------------------------------------------------------------
extern "C" void kernel_launch(void* const* d_in, const int* in_sizes, int n_in,
                              void* d_out, int out_size)
{
    const float* x     = (const float*)d_in[0];
    const float* mask  = (const float*)d_in[1];
    const float* wq    = (const float*)d_in[2];
    const float* bq    = (const float*)d_in[3];
    const float* wk    = (const float*)d_in[4];
    const float* bk    = (const float*)d_in[5];
    const float* wv    = (const float*)d_in[6];
    const float* bv    = (const float*)d_in[7];
    const float* wo    = (const float*)d_in[8];
    const float* bo    = (const float*)d_in[9];
    const float* nn_w1 = (const float*)d_in[10];
    const float* nn_b1 = (const float*)d_in[11];
    const float* nn_w2 = (const float*)d_in[12];
    const float* nn_b2 = (const float*)d_in[13];
    const float* f1    = (const float*)d_in[14];
    const float* f1b   = (const float*)d_in[15];
    const float* f2    = (const float*)d_in[16];
    const float* f2b   = (const float*)d_in[17];
    const float* g1    = (const float*)d_in[18];
    const float* be1   = (const float*)d_in[19];
    const float* g2    = (const float*)d_in[20];
    const float* be2   = (const float*)d_in[21];
    float* out = (float*)d_out;

    cudaFuncSetAttribute(k_main, cudaFuncAttributeMaxDynamicSharedMemorySize,
                         (int)sizeof(Smem));

    k_main<<<NBLK, 1024, sizeof(Smem)>>>(
        x, mask, wq, bq, wk, bk, wv, bv, wo, bo, nn_w1, nn_b1,
        nn_w2, nn_b2, f1, f1b, f2, f2b, g1, be1, g2, be2, out);
}

// round 14
// speedup vs baseline: 1.2401x; 1.0651x over previous
#include <cuda_runtime.h>
#include <cuda_fp16.h>
#include <math.h>

// Problem constants
#define B 8
#define L 256
#define D 16
#define H 128
#define DFF 128
#define EPSV 1e-6f

#define TI 16       // query rows per block
#define RI 8        // i-rows per thread
#define NBLK 128    // grid size (all co-resident: 128 <= 148 SMs @ 1 CTA/SM)

typedef unsigned long long u64;

// Scratch (device globals)
__device__ float  g_v   [B * L * D];
// [b][hq][j] : hq = 4-h group; uint4 = {kb(h0,h1), kb(h2,h3), ka(h0,h1), ka(h2,h3)} as f16x2 words
__device__ uint4  g_kbaT[B * (H/4) * L];
__device__ unsigned int g_bar;            // grid barrier ticket counter (monotonic)

// ---------------- helpers ----------------
__device__ __forceinline__ __half2 h2(unsigned u) {
    __half2 r; *reinterpret_cast<unsigned*>(&r) = u; return r;
}
__device__ __forceinline__ unsigned hbits(__half2 v) {
    return *reinterpret_cast<unsigned*>(&v);
}
// fused relu(a*1 + b) on f16x2 via fma.rn.relu (documented PTX, sm_80+)
__device__ __forceinline__ __half2 hfma2_relu(unsigned a, unsigned one2, __half2 b) {
    unsigned d;
    asm("fma.rn.relu.f16x2 %0,%1,%2,%3;" : "=r"(d) : "r"(a), "r"(one2), "r"(hbits(b)));
    return h2(d);
}
__device__ __forceinline__ void cpa16(void* dst_smem, const void* src_gmem) {
    unsigned d = (unsigned)__cvta_generic_to_shared(dst_smem);
    asm volatile("cp.async.cg.shared.global [%0], [%1], 16;" :: "r"(d), "l"(src_gmem) : "memory");
}

// ---------------------------------------------------------------------------
// Single fused kernel. 128 blocks x 1024 threads (1 CTA/SM).
// ---------------------------------------------------------------------------
struct __align__(16) Smem {
    unsigned qab16[TI * 132];    // interleaved f16x2 words: row*33 u4; u4 = {qa01,qa23,qb01,qb23}
    unsigned w2h[H / 2];         // f16x2
    float logitsP[2][TI * L];    // stage-A staging, then logit partials
    float maskS[TI * L];         // aliased after phase 2: ctxp/fp/csum
    float vT[D * 260];
    float wo[D * D];
    float f1[D * DFF];
    float f2T[D * 132];
    float xr[TI * D];
    float out1[TI * D];
    float f1b[DFF];
    float bo[D], f2b[D];
    float g1[D], be1[D], g2[D], be2[D];
};

__global__ __launch_bounds__(1024, 1) void k_main(
    const float* __restrict__ x,
    const float* __restrict__ mask,
    const float* __restrict__ wq, const float* __restrict__ bq,
    const float* __restrict__ wk, const float* __restrict__ bk,
    const float* __restrict__ wv, const float* __restrict__ bv,
    const float* __restrict__ wo_g, const float* __restrict__ bo_g,
    const float* __restrict__ nn_w1, const float* __restrict__ nn_b1,
    const float* __restrict__ w2_g, const float* __restrict__ b2_g,
    const float* __restrict__ f1_g, const float* __restrict__ f1b_g,
    const float* __restrict__ f2_g, const float* __restrict__ f2b_g,
    const float* __restrict__ g1_g, const float* __restrict__ be1_g,
    const float* __restrict__ g2_g, const float* __restrict__ be2_g,
    float* __restrict__ out)
{
    extern __shared__ char smem_raw[];
    Smem* s = reinterpret_cast<Smem*>(smem_raw);

    const int tid   = threadIdx.x;
    const int b     = blockIdx.x >> 4;
    const int iBase = (blockIdx.x & 15) << 4;

    // ---- mask cp.async immediately (consumed only at phase 2) ----
    {
        const float4* gm = reinterpret_cast<const float4*>(mask + (size_t)(b * L + iBase) * L);
        cpa16(reinterpret_cast<float4*>(s->maskS) + tid, gm + tid);   // 1024 f4
        asm volatile("cp.async.commit_group;" ::: "memory");
    }

    // =============== Stage A: per-block precompute (own 16 rows) ===========
    float* w1s = s->logitsP[0];              // 4096 = 32 x 128  (nn_w1)
    float* xs  = s->logitsP[1];              // 256
    float* stQ = s->logitsP[1] + 256;        // 256
    float* stK = s->logitsP[1] + 512;        // 256
    float* b1s = s->logitsP[1] + 768;        // 128

    reinterpret_cast<float4*>(w1s)[tid] = reinterpret_cast<const float4*>(nn_w1)[tid]; // 4096 floats
    if (tid < 256) {
        xs[tid]    = x[(b * L + iBase) * D + tid];
        s->xr[tid] = xs[tid];
    }
    if (tid < 128) b1s[tid] = nn_b1[tid];
    __syncthreads();

    const int rowA = tid >> 6;      // 0..15
    const int l64  = tid & 63;
    if (l64 < 48) {
        const int c = l64 & 15;
        const float* W    = (l64 < 16) ? wq : (l64 < 32 ? wk : wv);
        const float* bias = (l64 < 16) ? bq : (l64 < 32 ? bk : bv);
        float a = bias[c];
        #pragma unroll
        for (int d = 0; d < D; ++d) a = fmaf(xs[rowA * D + d], W[d * D + c], a);
        if      (l64 < 16) stQ[rowA * D + c] = a;
        else if (l64 < 32) stK[rowA * D + c] = a;
        else               g_v[(b * L + iBase + rowA) * D + c] = a;
    }
    __syncthreads();

    {
        const int hp = l64;             // 0..63  (pair of h)
        const int h0 = hp * 2;
        float qa0 = 0.f, qa1 = 0.f, qb0 = 0.f, qb1 = 0.f;
        float kb0 = b1s[h0], kb1 = b1s[h0 + 1];
        float ka0 = b1s[h0], ka1 = b1s[h0 + 1];
        #pragma unroll
        for (int d = 0; d < D; ++d) {
            const float qd = stQ[rowA * D + d];
            const float kd = stK[rowA * D + d];
            const float w1q0 = w1s[d * H + h0],        w1q1 = w1s[d * H + h0 + 1];
            const float w1k0 = w1s[(d + D) * H + h0],  w1k1 = w1s[(d + D) * H + h0 + 1];
            qa0 = fmaf(qd, w1q0, qa0);  qa1 = fmaf(qd, w1q1, qa1);
            qb0 = fmaf(qd, w1k0, qb0);  qb1 = fmaf(qd, w1k1, qb1);
            kb0 = fmaf(kd, w1k0, kb0);  kb1 = fmaf(kd, w1k1, kb1);
            ka0 = fmaf(kd, w1q0, ka0);  ka1 = fmaf(kd, w1q1, ka1);
        }
        // fp16 packing; interleaved qa/qb layout: u4 group = {qa01,qa23,qb01,qb23}
        const int hq = hp >> 1, sub = hp & 1;
        s->qab16[rowA * 132 + hq * 4 + sub]     = hbits(__floats2half2_rn(qa0, qa1));
        s->qab16[rowA * 132 + hq * 4 + 2 + sub] = hbits(__floats2half2_rn(qb0, qb1));
        unsigned* dst = reinterpret_cast<unsigned*>(g_kbaT)
                        + ((((size_t)(b * (H/4) + hq)) * L + (iBase + rowA)) << 2);
        dst[sub]     = hbits(__floats2half2_rn(kb0, kb1));
        dst[2 + sub] = hbits(__floats2half2_rn(ka0, ka1));
    }

    // ---- independent smem fills (no cross-block deps) before the barrier --
    {
        #pragma unroll
        for (int r = 0; r < 2; ++r) {
            const int e = tid + 1024 * r;              // < 2048
            const int h = e >> 4, d = e & 15;
            s->f2T[d * 132 + h] = f2_g[e];
        }
        if (tid < 512)
            reinterpret_cast<float4*>(s->f1)[tid] = reinterpret_cast<const float4*>(f1_g)[tid];
        if (tid < 64)  s->w2h[tid] = hbits(__floats2half2_rn(w2_g[2 * tid], w2_g[2 * tid + 1]));
        if (tid < 128) s->f1b[tid] = f1b_g[tid];
        if (tid < 256) s->wo[tid]  = wo_g[tid];
        if (tid < D) {
            s->bo[tid]  = bo_g[tid];  s->f2b[tid] = f2b_g[tid];
            s->g1[tid]  = g1_g[tid];  s->be1[tid] = be1_g[tid];
            s->g2[tid]  = g2_g[tid];  s->be2[tid] = be2_g[tid];
        }
    }
    const float b2x2 = 2.f * b2_g[0];

    // =============== Grid spin barrier (all 128 CTAs co-resident) ==========
    __syncthreads();
    __threadfence();
    if (tid == 0) {
        const unsigned int ticket = atomicAdd(&g_bar, 1u);
        const unsigned int target = (ticket / NBLK + 1u) * NBLK;
        volatile unsigned int* p = &g_bar;
        while (*p < target) {}
        __threadfence();
    }
    __syncthreads();

    // vT: transpose v[j][d] -> vT[d][260] (needs other blocks' g_v)
    {
        const float4 val = reinterpret_cast<const float4*>(g_v + b * L * D)[tid];  // 1024 f4
        const int j = tid >> 2, dq = tid & 3;
        s->vT[(dq * 4 + 0) * 260 + j] = val.x;
        s->vT[(dq * 4 + 1) * 260 + j] = val.y;
        s->vT[(dq * 4 + 2) * 260 + j] = val.z;
        s->vT[(dq * 4 + 3) * 260 + j] = val.w;
    }

    // ---------------- Phase 1: pairwise-MLP logits (fp16x2, barrier-free) --
    const int j  = tid & 255;          // fixed key column
    const int g  = (tid >> 8) & 1;     // i-half: rows g*8 .. g*8+7
    const int hh = tid >> 9;           // h-half: hq in [hh*16, hh*16+16)

    const uint4* gkba = g_kbaT + (size_t)(b * (H/4) + hh * 16) * L + j;  // stride L per hq
    const uint4* qabB = reinterpret_cast<const uint4*>(s->qab16) + (g * RI) * 33 + hh * 16;
    const uint2* w2p  = reinterpret_cast<const uint2*>(s->w2h) + hh * 16;

    const __half2 z2 = __float2half2_rn(0.f);
    const unsigned one2 = hbits(__float2half2_rn(1.f));
    __half2 acc0[RI], acc1[RI];
    #pragma unroll
    for (int r = 0; r < RI; ++r) { acc0[r] = z2; acc1[r] = z2; }

    uint4 C = gkba[0];

    #pragma unroll 4
    for (int c = 0; c < 16; ++c) {     // 16 chunks of 4 h
        uint4 N;
        if (c < 15) N = gkba[(c + 1) * L];
        const __half2 kb01 = h2(C.x), kb23 = h2(C.y);
        const __half2 ka01 = h2(C.z), ka23 = h2(C.w);
        const uint2 Wp = w2p[c];
        const __half2 w01 = h2(Wp.x), w23 = h2(Wp.y);
        #pragma unroll
        for (int r = 0; r < RI; ++r) {
            const uint4 A = qabB[r * 33 + c];   // {qa01, qa23, qb01, qb23}
            __half2 t0 = __hfma2(hfma2_relu(A.x, one2, kb01), w01, acc0[r]);
            acc0[r]    = __hfma2(hfma2_relu(A.z, one2, ka01), w01, t0);
            __half2 t1 = __hfma2(hfma2_relu(A.y, one2, kb23), w23, acc1[r]);
            acc1[r]    = __hfma2(hfma2_relu(A.w, one2, ka23), w23, t1);
        }
        C = N;
    }

    __syncthreads();   // stage-A staging in logitsP fully consumed block-wide
    #pragma unroll
    for (int r = 0; r < RI; ++r) {
        const float2 u  = __half22float2(acc0[r]);
        const float2 v2 = __half22float2(acc1[r]);
        s->logitsP[hh][(g * RI + r) * L + j] = (u.x + u.y) + (v2.x + v2.y);
    }

    asm volatile("cp.async.wait_group 0;" ::: "memory");
    __syncthreads();

    // ---------------- Phase 2: softmax (warps 0-15, 1 row each) ------------
    if (tid < 512) {
        const int r = tid >> 5, lane = tid & 31;
        const float* lp0 = s->logitsP[0] + r * L;
        const float* lp1 = s->logitsP[1] + r * L;
        const float* mr  = s->maskS + r * L;
        float vals[8];
        float mx = -INFINITY;
        #pragma unroll
        for (int t = 0; t < 8; ++t) {
            const int jj = lane + 32 * t;
            const float lg = lp0[jj] + lp1[jj] + b2x2 + mr[jj] * (-1e9f);
            vals[t] = lg;
            mx = fmaxf(mx, lg);
        }
        #pragma unroll
        for (int m = 16; m > 0; m >>= 1)
            mx = fmaxf(mx, __shfl_xor_sync(0xffffffffu, mx, m));
        float sum = 0.f;
        #pragma unroll
        for (int t = 0; t < 8; ++t) { vals[t] = __expf(vals[t] - mx); sum += vals[t]; }
        #pragma unroll
        for (int m = 16; m > 0; m >>= 1)
            sum += __shfl_xor_sync(0xffffffffu, sum, m);
        const float inv = 1.f / sum;
        #pragma unroll
        for (int t = 0; t < 8; ++t)
            s->logitsP[0][r * L + lane + 32 * t] = vals[t] * inv;
    }
    __syncthreads();

    // aliased scratch
    float* ctxp   = s->maskS;            // 1024
    float* fp     = s->maskS + 1024;     // 1024
    float* csum   = s->maskS + 2048;     // 256
    float* hidden = s->logitsP[1];       // 2048 (partials dead after phase 2)

    // ---------------- Phase 3: ctx = attn @ v (4 j-quarters) ---------------
    {
        const int q = tid >> 8, p = tid & 255;
        const int il = p >> 4, dl = p & 15;
        const float4* arow = reinterpret_cast<const float4*>(s->logitsP[0] + il * L + q * 64);
        const float4* vrow = reinterpret_cast<const float4*>(s->vT + dl * 260 + q * 64);
        float c2 = 0.f;
        #pragma unroll
        for (int t = 0; t < 16; ++t) {
            const float4 a4 = arow[t];
            const float4 v4 = vrow[t];
            c2 = fmaf(a4.x, v4.x, c2);
            c2 = fmaf(a4.y, v4.y, c2);
            c2 = fmaf(a4.z, v4.z, c2);
            c2 = fmaf(a4.w, v4.w, c2);
        }
        ctxp[q * 256 + p] = c2;
    }
    __syncthreads();

    // attn_out + residual + LN1 (first 256 threads)
    if (tid < 256) {
        const int il = tid >> 4, dl = tid & 15;
        csum[tid] = ctxp[tid] + ctxp[256 + tid] + ctxp[512 + tid] + ctxp[768 + tid];
        __syncwarp();
        float ao = s->bo[dl];
        #pragma unroll
        for (int e = 0; e < D; ++e)
            ao = fmaf(csum[il * D + e], s->wo[e * D + dl], ao);
        const float hval = s->xr[tid] + ao;   // RES=1
        float m = hval, sq = hval * hval;
        #pragma unroll
        for (int msk = 8; msk > 0; msk >>= 1) {
            m  += __shfl_xor_sync(0xffffffffu, m,  msk);
            sq += __shfl_xor_sync(0xffffffffu, sq, msk);
        }
        m *= (1.f / 16.f);
        const float var = sq * (1.f / 16.f) - m * m;
        s->out1[tid] = (hval - m) * rsqrtf(var + EPSV) * s->g1[dl] + s->be1[dl];
    }
    __syncthreads();

    // ---------------- Phase 4: FFN hidden (1024 threads, 2 i's each) -------
    {
        const int h = tid & 127;
        const int grp = tid >> 7;     // 0..7
        #pragma unroll
        for (int cc = 0; cc < 2; ++cc) {
            const int il = grp * 2 + cc;
            float a2 = s->f1b[h];
            #pragma unroll
            for (int d = 0; d < D; ++d)
                a2 = fmaf(s->out1[il * D + d], s->f1[d * DFF + h], a2);
            hidden[il * DFF + h] = fmaxf(a2, 0.f);
        }
    }
    __syncthreads();

    // f2 contraction (f2T, float4), 4 h-quarters
    {
        const int q = tid >> 8, p = tid & 255;
        const int il = p >> 4, dl = p & 15;
        const float4* hrow = reinterpret_cast<const float4*>(hidden + il * DFF + q * 32);
        const float4* frow = reinterpret_cast<const float4*>(s->f2T + dl * 132 + q * 32);
        float f = 0.f;
        #pragma unroll
        for (int t = 0; t < 8; ++t) {
            const float4 h4 = hrow[t];
            const float4 f4 = frow[t];
            f = fmaf(h4.x, f4.x, f);
            f = fmaf(h4.y, f4.y, f);
            f = fmaf(h4.z, f4.z, f);
            f = fmaf(h4.w, f4.w, f);
        }
        fp[q * 256 + p] = f;
    }
    __syncthreads();

    if (tid < 256) {
        const int il = tid >> 4, dl = tid & 15;
        const float f = s->f2b[dl] + fp[tid] + fp[256 + tid] + fp[512 + tid] + fp[768 + tid];
        const float hval = s->out1[tid] + f;   // RES=1
        float m = hval, sq = hval * hval;
        #pragma unroll
        for (int msk = 8; msk > 0; msk >>= 1) {
            m  += __shfl_xor_sync(0xffffffffu, m,  msk);
            sq += __shfl_xor_sync(0xffffffffu, sq, msk);
        }
        m *= (1.f / 16.f);
        const float var = sq * (1.f / 16.f) - m * m;
        const float o = (hval - m) * rsqrtf(var + EPSV) * s->g2[dl] + s->be2[dl];
        out[(size_t)(b * L + iBase + il) * D + dl] = o;
    }
}

// ---------------------------------------------------------------------------
extern "C" void kernel_launch(void* const* d_in, const int* in_sizes, int n_in,
                              void* d_out, int out_size)
{
    const float* x     = (const float*)d_in[0];
    const float* mask  = (const float*)d_in[1];
    const float* wq    = (const float*)d_in[2];
    const float* bq    = (const float*)d_in[3];
    const float* wk    = (const float*)d_in[4];
    const float* bk    = (const float*)d_in[5];
    const float* wv    = (const float*)d_in[6];
    const float* bv    = (const float*)d_in[7];
    const float* wo    = (const float*)d_in[8];
    const float* bo    = (const float*)d_in[9];
    const float* nn_w1 = (const float*)d_in[10];
    const float* nn_b1 = (const float*)d_in[11];
    const float* nn_w2 = (const float*)d_in[12];
    const float* nn_b2 = (const float*)d_in[13];
    const float* f1    = (const float*)d_in[14];
    const float* f1b   = (const float*)d_in[15];
    const float* f2    = (const float*)d_in[16];
    const float* f2b   = (const float*)d_in[17];
    const float* g1    = (const float*)d_in[18];
    const float* be1   = (const float*)d_in[19];
    const float* g2    = (const float*)d_in[20];
    const float* be2   = (const float*)d_in[21];
    float* out = (float*)d_out;

    cudaFuncSetAttribute(k_main, cudaFuncAttributeMaxDynamicSharedMemorySize,
                         (int)sizeof(Smem));

    k_main<<<NBLK, 1024, sizeof(Smem)>>>(
        x, mask, wq, bq, wk, bk, wv, bv, wo, bo, nn_w1, nn_b1,
        nn_w2, nn_b2, f1, f1b, f2, f2b, g1, be1, g2, be2, out);
}